// round 11
// baseline (speedup 1.0000x reference)
#include <cuda_runtime.h>
#include <math.h>
#include <stdint.h>

#define NDET 512
#define NC   81
#define HW   784
#define HW4  196           // HW / 4
#define NMS_THRESH 0.5
#define EPSV 1e-4
#define TAU  6e-6          // flag margin (iou units); worst-case f32 err ~1.2e-6
#define NTILE 36           // upper-triangular 8x8 tile count

// ---------------- scratch (static device memory) ----------------------------
__device__ __align__(16) float  g_Pf[2][NDET][HW];          // sorted probs (f32)
__device__ double        g_ud[2][NDET];                     // sorted row sums (f64)
__device__ __align__(16) float g_partial[2][2][NDET][NDET]; // [side][khalf] partials
__device__ __align__(16) unsigned int g_bits[2][NDET][16];  // packed mask rows
__device__ int           g_order[NDET];
__device__ int           g_ticket[2 * NTILE];               // per-tile finish count
__device__ int           g_done;                            // finished-tile count

// ---------------- 1. sigmoid-gather + inline rank + row sums (both sides) ---
__global__ void prob_kernel(const float* __restrict__ left,
                            const float* __restrict__ right,
                            const float* __restrict__ scores,
                            const int*   __restrict__ labels,
                            float*       __restrict__ out) {
    int n = blockIdx.x;
    int tid = threadIdx.x;

    if (n == 0) {   // reset cross-kernel state (stream-ordered before gemm)
        if (tid < 2 * NTILE) g_ticket[tid] = 0;
        if (tid == 2 * NTILE) g_done = 0;
    }

    // rank of n under stable argsort(-scores)
    __shared__ int s_cnt;
    if (tid == 0) s_cnt = 0;
    __syncthreads();
    float sn = __ldg(&scores[n]);
    int c = 0;
    for (int j = tid; j < NDET; j += 256) {
        float sj = __ldg(&scores[j]);
        c += (sj > sn) || (sj == sn && j < n);
    }
    for (int o = 16; o; o >>= 1) c += __shfl_down_sync(0xffffffffu, c, o);
    if ((tid & 31) == 0) atomicAdd(&s_cnt, c);
    __syncthreads();
    int r = s_cnt;
    if (tid == 0) g_order[r] = n;

    int cls = labels[n];
    __shared__ double red[8];
#pragma unroll
    for (int side = 0; side < 2; ++side) {
        const float* base = side ? right : left;
        const float4* row = (const float4*)(base + ((size_t)n * NC + cls) * HW);
        float4* orow = (float4*)(out + ((size_t)side * NDET + n) * HW);
        float4* prow = (float4*)g_Pf[side][r];

        double s = 0.0;
        if (tid < HW4) {
            float4 x = row[tid];
            float4 p;
            p.x = 1.0f / (1.0f + expf(-x.x));
            p.y = 1.0f / (1.0f + expf(-x.y));
            p.z = 1.0f / (1.0f + expf(-x.z));
            p.w = 1.0f / (1.0f + expf(-x.w));
            orow[tid] = p;
            prow[tid] = p;
            s = ((double)p.x + (double)p.y) + ((double)p.z + (double)p.w);
        }
        for (int o = 16; o; o >>= 1) s += __shfl_down_sync(0xffffffffu, s, o);
        if ((tid & 31) == 0) red[tid >> 5] = s;
        __syncthreads();
        if (tid == 0) {
            double tt = 0.0;
#pragma unroll
            for (int w = 0; w < 8; ++w) tt += red[w];
            g_ud[side][r] = tt;
        }
        __syncthreads();
    }
}

// ---------------- 2. fused: Gram partials + epilogue + refine + NMS ---------
// grid 144: blockIdx.x = z*NTILE + t, z = side*2 + khalf. Per tile, the second
// K-half block to finish combines halves (f64), thresholds, refines in-place,
// packs bits. The last of all 72 finishers runs skip-NMS + finalize inline.
__global__ void __launch_bounds__(256) gemm_fused_kernel(float* __restrict__ out,
                                                         int out_size) {
    int t = blockIdx.x % NTILE;
    int z = blockIdx.x / NTILE;
    int khalf = z & 1, side = z >> 1;
    int by = 0, rem = t;
    while (rem >= 8 - by) { rem -= 8 - by; ++by; }
    int bx = by + rem;                 // bx >= by (upper triangle)
    int arow0 = by * 64, brow0 = bx * 64;
    int kbeg = khalf ? 400 : 0;
    int kend = khalf ? HW : 400;

    __shared__ __align__(16) float As[16][68];
    __shared__ __align__(16) float Bs[16][68];
    __shared__ unsigned int words[64][2];
    __shared__ unsigned int rb[NDET * 16];      // 32KB, used only by last block
    __shared__ unsigned int s_sup[2][16];
    __shared__ int s_old, s_done;

    int tid = threadIdx.x;
    int lane = tid & 31;
    int tx = tid & 15, ty = tid >> 4;
    const float* P = &g_Pf[side][0][0];

    float s[4][4];
#pragma unroll
    for (int m = 0; m < 4; ++m)
#pragma unroll
        for (int n = 0; n < 4; ++n) s[m][n] = 0.0f;

    int rr = tid >> 2, kq = (tid & 3) * 4;
    const float* aptr = &P[(size_t)(arow0 + rr) * HW + kq];
    const float* bptr = &P[(size_t)(brow0 + rr) * HW + kq];

    float4 av = *(const float4*)&aptr[kbeg];
    float4 bv = *(const float4*)&bptr[kbeg];
    for (int kt = kbeg; kt < kend; kt += 16) {
        As[kq + 0][rr] = av.x; As[kq + 1][rr] = av.y;
        As[kq + 2][rr] = av.z; As[kq + 3][rr] = av.w;
        Bs[kq + 0][rr] = bv.x; Bs[kq + 1][rr] = bv.y;
        Bs[kq + 2][rr] = bv.z; Bs[kq + 3][rr] = bv.w;
        __syncthreads();
        if (kt + 16 < kend) {
            av = *(const float4*)&aptr[kt + 16];
            bv = *(const float4*)&bptr[kt + 16];
        }
        float tacc[4][4];
#pragma unroll
        for (int m = 0; m < 4; ++m)
#pragma unroll
            for (int n = 0; n < 4; ++n) tacc[m][n] = 0.0f;
#pragma unroll
        for (int kk = 0; kk < 16; ++kk) {
            float4 a4 = *(const float4*)&As[kk][ty * 4];
            float4 b4 = *(const float4*)&Bs[kk][tx * 4];
            float a[4] = {a4.x, a4.y, a4.z, a4.w};
            float bb[4] = {b4.x, b4.y, b4.z, b4.w};
#pragma unroll
            for (int m = 0; m < 4; ++m)
#pragma unroll
                for (int n = 0; n < 4; ++n) tacc[m][n] = fmaf(a[m], bb[n], tacc[m][n]);
        }
#pragma unroll
        for (int m = 0; m < 4; ++m)
#pragma unroll
            for (int n = 0; n < 4; ++n) s[m][n] = __fadd_rn(s[m][n], tacc[m][n]);
        __syncthreads();
    }

    // publish this half's partial, then take the tile ticket
    float* dst = &g_partial[side][khalf][0][0];
#pragma unroll
    for (int m = 0; m < 4; ++m) {
        int gi = arow0 + ty * 4 + m;
        float4 v = make_float4(s[m][0], s[m][1], s[m][2], s[m][3]);
        *(float4*)&dst[(size_t)gi * NDET + brow0 + tx * 4] = v;
    }
    __threadfence();            // release own partial
    __syncthreads();
    if (tid == 0) s_old = atomicAdd(&g_ticket[side * NTILE + t], 1);
    __syncthreads();
    if (s_old != 1) return;     // first finisher exits; second does epilogue
    __threadfence();            // acquire other half's partial

    // ---- epilogue: combine halves (f64), threshold, flag -------------------
    int oh = khalf ^ 1;
    const float* osrc = &g_partial[side][oh][0][0];
    unsigned int nib[4];
    double dens[4];
    unsigned int pend = 0;      // 16-bit mask over (m,n)
#pragma unroll
    for (int m = 0; m < 4; ++m) {
        int gi = arow0 + ty * 4 + m;
        double den = g_ud[side][gi] + EPSV;
        dens[m] = den;
        float4 o = __ldcg((const float4*)&osrc[(size_t)gi * NDET + brow0 + tx * 4]);
        float on[4] = {o.x, o.y, o.z, o.w};
        unsigned int nb = 0;
#pragma unroll
        for (int n = 0; n < 4; ++n) {
            double inter = (double)s[m][n] + (double)on[n];
            double mg = inter - 0.5 * den;
            if (mg >= 0.0) nb |= (1u << n);
            int gj = brow0 + tx * 4 + n;
            if (gj > gi && fabs(mg) <= TAU * den) pend |= (1u << (m * 4 + n));
        }
        nib[m] = nb;
    }

    // ---- warp-cooperative exact f64 refinement of flagged pairs ------------
    while (true) {
        unsigned int bal = __ballot_sync(0xffffffffu, pend != 0u);
        if (!bal) break;
        int srcl = __ffs(bal) - 1;
        unsigned int pw = __shfl_sync(0xffffffffu, pend, srcl);
        int e = __ffs(pw) - 1;
        int em = e >> 2, en = e & 3;
        int tsrc = (tid & ~31) | srcl;
        int gi = arow0 + (tsrc >> 4) * 4 + em;
        int gj = brow0 + (tsrc & 15) * 4 + en;
        const float4* Pi = (const float4*)g_Pf[side][gi];
        const float4* Pj = (const float4*)g_Pf[side][gj];
        double s0 = 0.0, s1 = 0.0, s2 = 0.0, s3 = 0.0;
#pragma unroll
        for (int q = 0; q < 7; ++q) {
            int k = lane + q * 32;
            float4 x = (k < HW4) ? Pi[k] : make_float4(0.f, 0.f, 0.f, 0.f);
            float4 y = (k < HW4) ? Pj[k] : make_float4(0.f, 0.f, 0.f, 0.f);
            s0 = fma((double)x.x, (double)y.x, s0);
            s1 = fma((double)x.y, (double)y.y, s1);
            s2 = fma((double)x.z, (double)y.z, s2);
            s3 = fma((double)x.w, (double)y.w, s3);
        }
        double sum = (s0 + s1) + (s2 + s3);
        for (int o = 16; o; o >>= 1) sum += __shfl_down_sync(0xffffffffu, sum, o);
        sum = __shfl_sync(0xffffffffu, sum, 0);
        if (lane == srcl) {
            if (sum / dens[em] >= NMS_THRESH) nib[em] |= (1u << en);
            else                              nib[em] &= ~(1u << en);
            pend &= ~(1u << e);
        }
    }

    // ---- pack bits ----------------------------------------------------------
    if (tid < 128) ((unsigned int*)words)[tid] = 0u;
    __syncthreads();
#pragma unroll
    for (int m = 0; m < 4; ++m)
        atomicOr(&words[ty * 4 + m][tx >> 3], nib[m] << ((tx & 7) * 4));
    __syncthreads();
    if (tid < 128)
        g_bits[side][arow0 + (tid >> 1)][(brow0 >> 5) + (tid & 1)] = words[tid >> 1][tid & 1];
    __threadfence();            // release bits
    __syncthreads();
    if (tid == 0) s_done = atomicAdd(&g_done, 1);
    __syncthreads();
    if (s_done != 2 * NTILE - 1) return;   // only the very last finisher continues
    __threadfence();            // acquire all bits

    // ---- inline skip-NMS + finalize (256 threads) ---------------------------
#pragma unroll
    for (int sd = 0; sd < 2; ++sd) {
        const uint4* src = (const uint4*)&g_bits[sd][0][0];
        for (int q = tid; q < NDET * 4; q += 256)
            ((uint4*)rb)[q] = __ldcg(&src[q]);
        __syncthreads();
        if (tid < 32) {
            unsigned int removed = 0;   // lane w<16 holds suppression word w
            int i = 0;
            while (true) {
                int rw = i >> 5, rbit = i & 31;
                unsigned int hi = (rbit == 31) ? 0u : (0xFFFFFFFFu << (rbit + 1));
                unsigned int m = (lane < 16) ? rb[i * 16 + lane] : 0u;
                if (lane < rw) m = 0u;
                else if (lane == rw) m &= hi;
                removed |= m;
                unsigned int cand = (lane < 16) ? ~removed : 0u;
                if (lane < rw) cand = 0u;
                else if (lane == rw) cand &= hi;
                unsigned int ball = __ballot_sync(0xffffffffu, cand != 0u);
                if (!ball) break;
                int w = __ffs(ball) - 1;
                unsigned int word = __shfl_sync(0xffffffffu, cand, w);
                i = w * 32 + __ffs(word) - 1;
            }
            if (lane < 16) s_sup[sd][lane] = removed;
        }
        __syncthreads();
    }

#pragma unroll
    for (int h = 0; h < 2; ++h) {
        int r = tid + h * 256;
        int n = g_order[r];
        bool valid = (g_ud[0][r] > 0.0) && (g_ud[1][r] > 0.0);
        bool supL = (s_sup[0][r >> 5] >> (r & 31)) & 1u;
        bool supR = (s_sup[1][r >> 5] >> (r & 31)) & 1u;
        float k = (valid && !supL && !supR) ? 1.0f : 0.0f;
        if (out_size >= 2 * NDET * HW + NDET)
            out[2 * NDET * HW + n] = k;
    }
}

// ---------------- launch -----------------------------------------------------
extern "C" void kernel_launch(void* const* d_in, const int* in_sizes, int n_in,
                              void* d_out, int out_size) {
    const float* left   = (const float*)d_in[0];
    const float* right  = (const float*)d_in[1];
    const float* scores = (const float*)d_in[2];
    const int*   labels = (const int*)d_in[3];
    float* out = (float*)d_out;
    (void)in_sizes; (void)n_in;

    prob_kernel<<<NDET, 256>>>(left, right, scores, labels, out);
    gemm_fused_kernel<<<4 * NTILE, 256>>>(out, out_size);
}

// round 13
// speedup vs baseline: 1.1537x; 1.1537x over previous
#include <cuda_runtime.h>
#include <math.h>
#include <stdint.h>

#define NDET 512
#define NC   81
#define HW   784
#define HW4  196           // HW / 4
#define NMS_THRESH 0.5
#define EPSV 1e-4
#define TAU  6e-6          // flag margin (iou units); worst-case f32 err ~1.2e-6
#define NTILE 36           // upper-triangular 8x8 tile count

// ---------------- scratch (static device memory) ----------------------------
__device__ __align__(16) float  g_Pf[2][NDET][HW];          // sorted probs (f32)
__device__ double        g_ud[2][NDET];                     // sorted row sums (f64)
__device__ __align__(16) float g_partial[2][2][NDET][NDET]; // [side][khalf] partials
__device__ __align__(16) unsigned int g_bits[2][NDET][16];  // packed mask rows
__device__ int           g_order[NDET];
__device__ int           g_done;                            // epilogue done counter

// ---------------- 1. sigmoid-gather + inline rank + row sums ----------------
// grid (512, 2) x 256 thr: block (n, side). Rank recomputed per side (L2-hot).
__global__ void prob_kernel(const float* __restrict__ left,
                            const float* __restrict__ right,
                            const float* __restrict__ scores,
                            const int*   __restrict__ labels,
                            float*       __restrict__ out) {
    int n = blockIdx.x;
    int side = blockIdx.y;
    int tid = threadIdx.x;

    if (n == 0 && side == 0 && tid == 0) g_done = 0;

    // rank of n under stable argsort(-scores)
    __shared__ int s_cnt;
    if (tid == 0) s_cnt = 0;
    __syncthreads();
    float sn = __ldg(&scores[n]);
    int c = 0;
    for (int j = tid; j < NDET; j += 256) {
        float sj = __ldg(&scores[j]);
        c += (sj > sn) || (sj == sn && j < n);
    }
    for (int o = 16; o; o >>= 1) c += __shfl_down_sync(0xffffffffu, c, o);
    if ((tid & 31) == 0) atomicAdd(&s_cnt, c);
    __syncthreads();
    int r = s_cnt;
    if (side == 0 && tid == 0) g_order[r] = n;

    int cls = labels[n];
    const float* base = side ? right : left;
    const float4* row = (const float4*)(base + ((size_t)n * NC + cls) * HW);
    float4* orow = (float4*)(out + ((size_t)side * NDET + n) * HW);
    float4* prow = (float4*)g_Pf[side][r];

    double s = 0.0;
    if (tid < HW4) {
        float4 x = row[tid];
        float4 p;
        p.x = 1.0f / (1.0f + expf(-x.x));
        p.y = 1.0f / (1.0f + expf(-x.y));
        p.z = 1.0f / (1.0f + expf(-x.z));
        p.w = 1.0f / (1.0f + expf(-x.w));
        orow[tid] = p;
        prow[tid] = p;
        s = ((double)p.x + (double)p.y) + ((double)p.z + (double)p.w);
    }
    __shared__ double red[8];
    for (int o = 16; o; o >>= 1) s += __shfl_down_sync(0xffffffffu, s, o);
    if ((tid & 31) == 0) red[tid >> 5] = s;
    __syncthreads();
    if (tid == 0) {
        double tt = 0.0;
#pragma unroll
        for (int w = 0; w < 8; ++w) tt += red[w];
        g_ud[side][r] = tt;
    }
}

// ---------------- 2. f32 Gram partials: compact tri grid + reg prefetch -----
// grid 144 linear: blockIdx.x = z*NTILE + t, z = side*2 + khalf. All blocks live.
// (Byte-identical to the measured-fast R10 version — do not touch.)
__global__ void __launch_bounds__(256) gemm_partial_kernel() {
    int t = blockIdx.x % NTILE;
    int z = blockIdx.x / NTILE;
    int khalf = z & 1, side = z >> 1;
    int by = 0, rem = t;
    while (rem >= 8 - by) { rem -= 8 - by; ++by; }
    int bx = by + rem;                 // bx >= by (upper triangle)
    int arow0 = by * 64, brow0 = bx * 64;
    int kbeg = khalf ? 400 : 0;
    int kend = khalf ? HW : 400;

    __shared__ __align__(16) float As[16][68];
    __shared__ __align__(16) float Bs[16][68];
    int tid = threadIdx.x;
    int tx = tid & 15, ty = tid >> 4;
    const float* P = &g_Pf[side][0][0];

    float s[4][4];
#pragma unroll
    for (int m = 0; m < 4; ++m)
#pragma unroll
        for (int n = 0; n < 4; ++n) s[m][n] = 0.0f;

    int rr = tid >> 2, kq = (tid & 3) * 4;
    const float* aptr = &P[(size_t)(arow0 + rr) * HW + kq];
    const float* bptr = &P[(size_t)(brow0 + rr) * HW + kq];

    float4 av = *(const float4*)&aptr[kbeg];
    float4 bv = *(const float4*)&bptr[kbeg];
    for (int kt = kbeg; kt < kend; kt += 16) {
        As[kq + 0][rr] = av.x; As[kq + 1][rr] = av.y;
        As[kq + 2][rr] = av.z; As[kq + 3][rr] = av.w;
        Bs[kq + 0][rr] = bv.x; Bs[kq + 1][rr] = bv.y;
        Bs[kq + 2][rr] = bv.z; Bs[kq + 3][rr] = bv.w;
        __syncthreads();
        if (kt + 16 < kend) {           // prefetch next k-tile during compute
            av = *(const float4*)&aptr[kt + 16];
            bv = *(const float4*)&bptr[kt + 16];
        }
        float tacc[4][4];
#pragma unroll
        for (int m = 0; m < 4; ++m)
#pragma unroll
            for (int n = 0; n < 4; ++n) tacc[m][n] = 0.0f;
#pragma unroll
        for (int kk = 0; kk < 16; ++kk) {
            float4 a4 = *(const float4*)&As[kk][ty * 4];
            float4 b4 = *(const float4*)&Bs[kk][tx * 4];
            float a[4] = {a4.x, a4.y, a4.z, a4.w};
            float bb[4] = {b4.x, b4.y, b4.z, b4.w};
#pragma unroll
            for (int m = 0; m < 4; ++m)
#pragma unroll
                for (int n = 0; n < 4; ++n) tacc[m][n] = fmaf(a[m], bb[n], tacc[m][n]);
        }
#pragma unroll
        for (int m = 0; m < 4; ++m)
#pragma unroll
            for (int n = 0; n < 4; ++n) s[m][n] = __fadd_rn(s[m][n], tacc[m][n]);
        __syncthreads();
    }

    float* dst = &g_partial[side][khalf][0][0];
#pragma unroll
    for (int m = 0; m < 4; ++m) {
        int gi = arow0 + ty * 4 + m;
        float4 v = make_float4(s[m][0], s[m][1], s[m][2], s[m][3]);
        *(float4*)&dst[(size_t)gi * NDET + brow0 + tx * 4] = v;
    }
}

// ---------------- 3. epilogue + inline refine + (last block) NMS/finalize ---
// grid (256, 2), 256 threads: 2 rows/block. Last done block runs skip-NMS.
__global__ void epilogue_kernel(float* __restrict__ out, int out_size) {
    int side = blockIdx.y;
    int tid = threadIdx.x;
    int lane = tid & 31;
    int rloc = tid >> 7;                 // 0..1 (warp-uniform)
    int i = blockIdx.x * 2 + rloc;
    int tt = tid & 127;
    __shared__ __align__(16) unsigned int rb[NDET * 16]; // 32 KB; tail use only
    __shared__ __align__(16) unsigned int words[2][16];
    __shared__ unsigned int s_sup[2][16];
    __shared__ int s_done;
    if (tid < 32) words[tid >> 4][tid & 15] = 0;
    __syncthreads();

    double den = g_ud[side][i] + EPSV;
    int j0 = tt * 4;
    float4 a = *(const float4*)&g_partial[side][0][i][j0];
    float4 b = *(const float4*)&g_partial[side][1][i][j0];
    float pa[4] = {a.x, a.y, a.z, a.w};
    float pb[4] = {b.x, b.y, b.z, b.w};
    unsigned int nib = 0, pend = 0;
#pragma unroll
    for (int n = 0; n < 4; ++n) {
        double inter = (double)pa[n] + (double)pb[n];
        double mg = inter - 0.5 * den;
        if (mg >= 0.0) nib |= (1u << n);
        if (j0 + n > i && fabs(mg) <= TAU * den) pend |= (1u << n);
    }

    // warp-cooperative exact refinement of flagged pairs (i is warp-uniform)
    const float4* Pi = (const float4*)g_Pf[side][i];
    while (true) {
        unsigned int bal = __ballot_sync(0xffffffffu, pend != 0u);
        if (!bal) break;
        int src = __ffs(bal) - 1;
        unsigned int pw = __shfl_sync(0xffffffffu, pend, src);
        int n = __ffs(pw) - 1;
        int gj = __shfl_sync(0xffffffffu, j0, src) + n;
        const float4* Pj = (const float4*)g_Pf[side][gj];
        double s0 = 0.0, s1 = 0.0, s2 = 0.0, s3 = 0.0;
#pragma unroll
        for (int q = 0; q < 7; ++q) {           // 196 float4 per row
            int k = lane + q * 32;
            float4 x = (k < HW4) ? Pi[k] : make_float4(0.f, 0.f, 0.f, 0.f);
            float4 y = (k < HW4) ? Pj[k] : make_float4(0.f, 0.f, 0.f, 0.f);
            s0 = fma((double)x.x, (double)y.x, s0);
            s1 = fma((double)x.y, (double)y.y, s1);
            s2 = fma((double)x.z, (double)y.z, s2);
            s3 = fma((double)x.w, (double)y.w, s3);
        }
        double sum = (s0 + s1) + (s2 + s3);
        for (int o = 16; o; o >>= 1) sum += __shfl_down_sync(0xffffffffu, sum, o);
        sum = __shfl_sync(0xffffffffu, sum, 0);
        if (lane == src) {
            if (sum / den >= NMS_THRESH) nib |= (1u << n);
            else                         nib &= ~(1u << n);
            pend &= ~(1u << n);
        }
    }

    atomicOr(&words[rloc][tt >> 3], nib << ((tt & 7) * 4));
    __syncthreads();
    if (tid < 32)
        g_bits[side][blockIdx.x * 2 + (tid >> 4)][tid & 15] = words[tid >> 4][tid & 15];

    // ---- done-counter: last finished block runs NMS + finalize -------------
    __threadfence();                        // release our bits
    __syncthreads();
    if (tid == 0) s_done = atomicAdd(&g_done, 1);
    __syncthreads();
    if (s_done != 2 * (NDET / 2) - 1) return;
    __threadfence();                        // acquire all bits

#pragma unroll
    for (int sd = 0; sd < 2; ++sd) {
        const uint4* src = (const uint4*)&g_bits[sd][0][0];
        for (int q = tid; q < NDET * 4; q += 256)
            ((uint4*)rb)[q] = __ldcg(&src[q]);
        __syncthreads();
        if (tid < 32) {
            unsigned int removed = 0;   // lane w<16 holds suppression word w
            int ii = 0;                 // top-ranked row always kept
            while (true) {
                int rw = ii >> 5, rbit = ii & 31;
                unsigned int hi = (rbit == 31) ? 0u : (0xFFFFFFFFu << (rbit + 1));
                unsigned int m = (lane < 16) ? rb[ii * 16 + lane] : 0u;
                if (lane < rw) m = 0u;
                else if (lane == rw) m &= hi;
                removed |= m;
                unsigned int cand = (lane < 16) ? ~removed : 0u;
                if (lane < rw) cand = 0u;
                else if (lane == rw) cand &= hi;
                unsigned int ball = __ballot_sync(0xffffffffu, cand != 0u);
                if (!ball) break;
                int w = __ffs(ball) - 1;
                unsigned int word = __shfl_sync(0xffffffffu, cand, w);
                ii = w * 32 + __ffs(word) - 1;
            }
            if (lane < 16) s_sup[sd][lane] = removed;
        }
        __syncthreads();
    }

#pragma unroll
    for (int h = 0; h < 2; ++h) {
        int r = tid + h * 256;
        int n = g_order[r];
        bool valid = (g_ud[0][r] > 0.0) && (g_ud[1][r] > 0.0);
        bool supL = (s_sup[0][r >> 5] >> (r & 31)) & 1u;
        bool supR = (s_sup[1][r >> 5] >> (r & 31)) & 1u;
        float k = (valid && !supL && !supR) ? 1.0f : 0.0f;
        if (out_size >= 2 * NDET * HW + NDET)
            out[2 * NDET * HW + n] = k;
    }
}

// ---------------- launch -----------------------------------------------------
extern "C" void kernel_launch(void* const* d_in, const int* in_sizes, int n_in,
                              void* d_out, int out_size) {
    const float* left   = (const float*)d_in[0];
    const float* right  = (const float*)d_in[1];
    const float* scores = (const float*)d_in[2];
    const int*   labels = (const int*)d_in[3];
    float* out = (float*)d_out;
    (void)in_sizes; (void)n_in;

    dim3 pgrid(NDET, 2);
    prob_kernel<<<pgrid, 256>>>(left, right, scores, labels, out);
    gemm_partial_kernel<<<4 * NTILE, 256>>>();
    dim3 egrid(NDET / 2, 2);
    epilogue_kernel<<<egrid, 256>>>(out, out_size);
}